// round 1
// baseline (speedup 1.0000x reference)
#include <cuda_runtime.h>
#include <math.h>
#include <stdint.h>

#define NTOK 8192
#define DIN  1024
#define HID  4096
#define TOPKC 103
#define THRESH 2048

#define BM 128
#define BN 64
#define BK 16

// ---------------- scratch (__device__ globals; no allocation allowed) -------
__device__ __align__(16) signed char g_qx[(size_t)NTOK * DIN];   // 8 MB
__device__ __align__(16) signed char g_qw[(size_t)HID * DIN];    // 4 MB
__device__ float g_sx[NTOK];
__device__ float g_sw[HID];
__device__ float g_qb[HID];
__device__ int   g_counts[HID];
__device__ __align__(16) float g_h[(size_t)NTOK * HID];          // 128 MB

// ---------------- quantization helpers --------------------------------------
__global__ void zero_counts_kernel() {
    int i = blockIdx.x * blockDim.x + threadIdx.x;
    if (i < HID) g_counts[i] = 0;
}

// per-row abs-max quantization, matching jnp: s = max(absmax,1e-5)/127,
// q = clip(rint(v/s), -128, 127); store int8 and scale.
__global__ void quant_rows_kernel(const float* __restrict__ src, int which) {
    float* scales = which ? g_sw : g_sx;
    signed char* q = which ? g_qw : g_qx;
    int row = blockIdx.x;
    const float* r = src + (size_t)row * DIN;

    float amax = 0.f;
    {
        int i = threadIdx.x * 4;  // 256 threads * 4 = 1024 = DIN
        float4 v = *(const float4*)(r + i);
        amax = fmaxf(fmaxf(fabsf(v.x), fabsf(v.y)), fmaxf(fabsf(v.z), fabsf(v.w)));
    }
    __shared__ float red[256];
    red[threadIdx.x] = amax;
    __syncthreads();
    for (int s = 128; s; s >>= 1) {
        if (threadIdx.x < s) red[threadIdx.x] = fmaxf(red[threadIdx.x], red[threadIdx.x + s]);
        __syncthreads();
    }
    float scale = fmaxf(red[0], 1e-5f) / 127.0f;
    if (threadIdx.x == 0) scales[row] = scale;

    {
        int i = threadIdx.x * 4;
        float4 v = *(const float4*)(r + i);
        char4 o;
        o.x = (signed char)(int)fminf(127.f, fmaxf(-128.f, rintf(v.x / scale)));
        o.y = (signed char)(int)fminf(127.f, fmaxf(-128.f, rintf(v.y / scale)));
        o.z = (signed char)(int)fminf(127.f, fmaxf(-128.f, rintf(v.z / scale)));
        o.w = (signed char)(int)fminf(127.f, fmaxf(-128.f, rintf(v.w / scale)));
        *(char4*)(q + (size_t)row * DIN + i) = o;
    }
}

// b1 is quantized as ONE channel over its last (only) dim of 4096.
__global__ void quant_bias_kernel(const float* __restrict__ b1) {
    __shared__ float red[256];
    float amax = 0.f;
    for (int i = threadIdx.x; i < HID; i += 256) amax = fmaxf(amax, fabsf(b1[i]));
    red[threadIdx.x] = amax;
    __syncthreads();
    for (int s = 128; s; s >>= 1) {
        if (threadIdx.x < s) red[threadIdx.x] = fmaxf(red[threadIdx.x], red[threadIdx.x + s]);
        __syncthreads();
    }
    float scale = fmaxf(red[0], 1e-5f) / 127.0f;
    for (int i = threadIdx.x; i < HID; i += 256) {
        float qv = fminf(127.f, fmaxf(-128.f, rintf(b1[i] / scale)));
        g_qb[i] = qv * scale;
    }
}

// ---------------- topk predictor: count positives of (x[:, :103] @ W1[:, :103]^T + b1)
__global__ void __launch_bounds__(256, 2)
topk_count_kernel(const float* __restrict__ x, const float* __restrict__ W1,
                  const float* __restrict__ b1) {
    __shared__ __align__(16) float As[BK][BM];
    __shared__ __align__(16) float Bs[BK][BN];
    __shared__ int cnt[BN];

    int tid = threadIdx.x;
    int ty = tid >> 4, tx = tid & 15;
    int i0 = blockIdx.y * BM, h0 = blockIdx.x * BN;

    float acc[8][4];
#pragma unroll
    for (int m = 0; m < 8; m++)
#pragma unroll
        for (int n = 0; n < 4; n++) acc[m][n] = 0.f;

    for (int k0 = 0; k0 < 112; k0 += BK) {  // 112 = ceil16(103)
#pragma unroll
        for (int l = 0; l < 2; l++) {
            int idx = tid + l * 256, rr = idx >> 2, c4 = idx & 3;
            float4 v = *(const float4*)(x + (size_t)(i0 + rr) * DIN + k0 + c4 * 4);
            int kb = k0 + c4 * 4;
            if (kb + 0 >= TOPKC) v.x = 0.f;
            if (kb + 1 >= TOPKC) v.y = 0.f;
            if (kb + 2 >= TOPKC) v.z = 0.f;
            if (kb + 3 >= TOPKC) v.w = 0.f;
            As[c4 * 4 + 0][rr] = v.x; As[c4 * 4 + 1][rr] = v.y;
            As[c4 * 4 + 2][rr] = v.z; As[c4 * 4 + 3][rr] = v.w;
        }
        {
            int rr = tid >> 2, c4 = tid & 3;
            float4 v = *(const float4*)(W1 + (size_t)(h0 + rr) * DIN + k0 + c4 * 4);
            int kb = k0 + c4 * 4;
            if (kb + 0 >= TOPKC) v.x = 0.f;
            if (kb + 1 >= TOPKC) v.y = 0.f;
            if (kb + 2 >= TOPKC) v.z = 0.f;
            if (kb + 3 >= TOPKC) v.w = 0.f;
            Bs[c4 * 4 + 0][rr] = v.x; Bs[c4 * 4 + 1][rr] = v.y;
            Bs[c4 * 4 + 2][rr] = v.z; Bs[c4 * 4 + 3][rr] = v.w;
        }
        __syncthreads();
#pragma unroll
        for (int kk = 0; kk < BK; kk++) {
            float4 a0 = *(const float4*)&As[kk][ty * 8];
            float4 a1 = *(const float4*)&As[kk][ty * 8 + 4];
            float4 b  = *(const float4*)&Bs[kk][tx * 4];
            float av[8] = {a0.x, a0.y, a0.z, a0.w, a1.x, a1.y, a1.z, a1.w};
            float bv[4] = {b.x, b.y, b.z, b.w};
#pragma unroll
            for (int m = 0; m < 8; m++)
#pragma unroll
                for (int n = 0; n < 4; n++) acc[m][n] += av[m] * bv[n];
        }
        __syncthreads();
    }

    if (tid < BN) cnt[tid] = 0;
    __syncthreads();
#pragma unroll
    for (int n = 0; n < 4; n++) {
        float bv = b1[h0 + tx * 4 + n];
        int c = 0;
#pragma unroll
        for (int m = 0; m < 8; m++)
            if (acc[m][n] + bv > 0.f) c++;
        atomicAdd(&cnt[tx * 4 + n], c);
    }
    __syncthreads();
    if (tid < BN) atomicAdd(&g_counts[h0 + tid], cnt[tid]);
}

// ---------------- main fused GEMM: fp32 prod + int8(dp4a) q_pre -> select -> gelu -> g_h
__device__ __forceinline__ float gelu_exact(float v) {
    return 0.5f * v * (1.0f + erff(v * 0.70710678118654752440f));
}

__global__ void __launch_bounds__(256, 2)
mlp1_kernel(const float* __restrict__ x, const float* __restrict__ W1,
            const float* __restrict__ b1) {
    __shared__ __align__(16) float As[BK][BM];
    __shared__ __align__(16) float Bs[BK][BN];
    __shared__ __align__(16) int QA[4][BM];
    __shared__ __align__(16) int QB[4][BN];

    int tid = threadIdx.x;
    int ty = tid >> 4, tx = tid & 15;
    int i0 = blockIdx.y * BM, h0 = blockIdx.x * BN;

    float accf[8][4];
    int   acci[8][4];
#pragma unroll
    for (int m = 0; m < 8; m++)
#pragma unroll
        for (int n = 0; n < 4; n++) { accf[m][n] = 0.f; acci[m][n] = 0; }

    const int* qx4 = (const int*)g_qx;
    const int* qw4 = (const int*)g_qw;

    for (int k0 = 0; k0 < DIN; k0 += BK) {
#pragma unroll
        for (int l = 0; l < 2; l++) {
            int idx = tid + l * 256, rr = idx >> 2, c4 = idx & 3;
            float4 v = *(const float4*)(x + (size_t)(i0 + rr) * DIN + k0 + c4 * 4);
            As[c4 * 4 + 0][rr] = v.x; As[c4 * 4 + 1][rr] = v.y;
            As[c4 * 4 + 2][rr] = v.z; As[c4 * 4 + 3][rr] = v.w;
            QA[c4][rr] = qx4[(size_t)(i0 + rr) * (DIN / 4) + (k0 >> 2) + c4];
        }
        {
            int rr = tid >> 2, c4 = tid & 3;
            float4 v = *(const float4*)(W1 + (size_t)(h0 + rr) * DIN + k0 + c4 * 4);
            Bs[c4 * 4 + 0][rr] = v.x; Bs[c4 * 4 + 1][rr] = v.y;
            Bs[c4 * 4 + 2][rr] = v.z; Bs[c4 * 4 + 3][rr] = v.w;
            QB[c4][rr] = qw4[(size_t)(h0 + rr) * (DIN / 4) + (k0 >> 2) + c4];
        }
        __syncthreads();

#pragma unroll
        for (int kk = 0; kk < BK; kk++) {
            float4 a0 = *(const float4*)&As[kk][ty * 8];
            float4 a1 = *(const float4*)&As[kk][ty * 8 + 4];
            float4 b  = *(const float4*)&Bs[kk][tx * 4];
            float av[8] = {a0.x, a0.y, a0.z, a0.w, a1.x, a1.y, a1.z, a1.w};
            float bv[4] = {b.x, b.y, b.z, b.w};
#pragma unroll
            for (int m = 0; m < 8; m++)
#pragma unroll
                for (int n = 0; n < 4; n++) accf[m][n] += av[m] * bv[n];
        }
#pragma unroll
        for (int g4 = 0; g4 < 4; g4++) {
            int4 qa0 = *(const int4*)&QA[g4][ty * 8];
            int4 qa1 = *(const int4*)&QA[g4][ty * 8 + 4];
            int4 qb  = *(const int4*)&QB[g4][tx * 4];
            int qav[8] = {qa0.x, qa0.y, qa0.z, qa0.w, qa1.x, qa1.y, qa1.z, qa1.w};
            int qbv[4] = {qb.x, qb.y, qb.z, qb.w};
#pragma unroll
            for (int m = 0; m < 8; m++)
#pragma unroll
                for (int n = 0; n < 4; n++) acci[m][n] = __dp4a(qav[m], qbv[n], acci[m][n]);
        }
        __syncthreads();
    }

    // epilogue: channel select + exact gelu, vectorized float4 store
    float b1v[4], swv[4], qbv[4];
    bool fsel[4];
#pragma unroll
    for (int n = 0; n < 4; n++) {
        int h = h0 + tx * 4 + n;
        b1v[n] = b1[h];
        swv[n] = g_sw[h];
        qbv[n] = g_qb[h];
        fsel[n] = g_counts[h] > THRESH;
    }
#pragma unroll
    for (int m = 0; m < 8; m++) {
        int i = i0 + ty * 8 + m;
        float sxv = g_sx[i];
        float vals[4];
#pragma unroll
        for (int n = 0; n < 4; n++) {
            float v = fsel[n] ? (accf[m][n] + b1v[n])
                              : fmaf(sxv * swv[n], (float)acci[m][n], qbv[n]);
            vals[n] = gelu_exact(v);
        }
        float4 o = make_float4(vals[0], vals[1], vals[2], vals[3]);
        *(float4*)&g_h[(size_t)i * HID + h0 + tx * 4] = o;
    }
}

// ---------------- second layer: out = g_h @ W2^T + b2 -----------------------
__global__ void __launch_bounds__(256, 2)
mlp2_kernel(const float* __restrict__ W2, const float* __restrict__ b2,
            float* __restrict__ out) {
    __shared__ __align__(16) float As[BK][BM];
    __shared__ __align__(16) float Bs[BK][BN];

    int tid = threadIdx.x;
    int ty = tid >> 4, tx = tid & 15;
    int i0 = blockIdx.y * BM, d0 = blockIdx.x * BN;

    float acc[8][4];
#pragma unroll
    for (int m = 0; m < 8; m++)
#pragma unroll
        for (int n = 0; n < 4; n++) acc[m][n] = 0.f;

    for (int k0 = 0; k0 < HID; k0 += BK) {
#pragma unroll
        for (int l = 0; l < 2; l++) {
            int idx = tid + l * 256, rr = idx >> 2, c4 = idx & 3;
            float4 v = *(const float4*)&g_h[(size_t)(i0 + rr) * HID + k0 + c4 * 4];
            As[c4 * 4 + 0][rr] = v.x; As[c4 * 4 + 1][rr] = v.y;
            As[c4 * 4 + 2][rr] = v.z; As[c4 * 4 + 3][rr] = v.w;
        }
        {
            int rr = tid >> 2, c4 = tid & 3;
            float4 v = *(const float4*)(W2 + (size_t)(d0 + rr) * HID + k0 + c4 * 4);
            Bs[c4 * 4 + 0][rr] = v.x; Bs[c4 * 4 + 1][rr] = v.y;
            Bs[c4 * 4 + 2][rr] = v.z; Bs[c4 * 4 + 3][rr] = v.w;
        }
        __syncthreads();
#pragma unroll
        for (int kk = 0; kk < BK; kk++) {
            float4 a0 = *(const float4*)&As[kk][ty * 8];
            float4 a1 = *(const float4*)&As[kk][ty * 8 + 4];
            float4 b  = *(const float4*)&Bs[kk][tx * 4];
            float av[8] = {a0.x, a0.y, a0.z, a0.w, a1.x, a1.y, a1.z, a1.w};
            float bv[4] = {b.x, b.y, b.z, b.w};
#pragma unroll
            for (int m = 0; m < 8; m++)
#pragma unroll
                for (int n = 0; n < 4; n++) acc[m][n] += av[m] * bv[n];
        }
        __syncthreads();
    }

    float4 bb = *(const float4*)(b2 + d0 + tx * 4);
    float bv[4] = {bb.x, bb.y, bb.z, bb.w};
#pragma unroll
    for (int m = 0; m < 8; m++) {
        int i = i0 + ty * 8 + m;
        float4 o = make_float4(acc[m][0] + bv[0], acc[m][1] + bv[1],
                               acc[m][2] + bv[2], acc[m][3] + bv[3]);
        *(float4*)(out + (size_t)i * DIN + d0 + tx * 4) = o;
    }
}

// ---------------- launch -----------------------------------------------------
extern "C" void kernel_launch(void* const* d_in, const int* in_sizes, int n_in,
                              void* d_out, int out_size) {
    const float* x  = (const float*)d_in[0];   // [4,2048,1024] -> [8192,1024]
    const float* W1 = (const float*)d_in[1];   // [4096,1024]
    const float* b1 = (const float*)d_in[2];   // [4096]
    const float* W2 = (const float*)d_in[3];   // [1024,4096]
    const float* b2 = (const float*)d_in[4];   // [1024]
    float* out = (float*)d_out;                // [8192,1024]

    zero_counts_kernel<<<HID / 256, 256>>>();
    quant_rows_kernel<<<NTOK, 256>>>(x, 0);
    quant_rows_kernel<<<HID, 256>>>(W1, 1);
    quant_bias_kernel<<<1, 256>>>(b1);

    dim3 g1(HID / BN, NTOK / BM);   // (64, 64)
    topk_count_kernel<<<g1, 256>>>(x, W1, b1);
    mlp1_kernel<<<g1, 256>>>(x, W1, b1);

    dim3 g2(DIN / BN, NTOK / BM);   // (16, 64)
    mlp2_kernel<<<g2, 256>>>(W2, b2, out);
}

// round 2
// speedup vs baseline: 1.0003x; 1.0003x over previous
#include <cuda_runtime.h>
#include <math.h>
#include <stdint.h>

#define NTOK 8192
#define DIN  1024
#define HID  4096
#define TOPKC 103
#define THRESH 2048

#define BM 128
#define BN 64
#define BK 16

// ---------------- scratch (__device__ globals; no allocation allowed) -------
__device__ __align__(16) signed char g_qx[(size_t)NTOK * DIN];   // 8 MB
__device__ __align__(16) signed char g_qw[(size_t)HID * DIN];    // 4 MB
__device__ float g_sx[NTOK];
__device__ float g_sw[HID];
__device__ float g_qb[HID];
__device__ int   g_counts[HID];
__device__ __align__(16) float g_h[(size_t)NTOK * HID];          // 128 MB

// ---------------- quantization helpers --------------------------------------
__global__ void zero_counts_kernel() {
    int i = blockIdx.x * blockDim.x + threadIdx.x;
    if (i < HID) g_counts[i] = 0;
}

// per-row abs-max quantization, matching jnp: s = max(absmax,1e-5)/127,
// q = clip(rint(v/s), -128, 127); store int8 and scale.
__global__ void quant_rows_kernel(const float* __restrict__ src, int which) {
    float* scales = which ? g_sw : g_sx;
    signed char* q = which ? g_qw : g_qx;
    int row = blockIdx.x;
    const float* r = src + (size_t)row * DIN;

    float amax = 0.f;
    {
        int i = threadIdx.x * 4;  // 256 threads * 4 = 1024 = DIN
        float4 v = *(const float4*)(r + i);
        amax = fmaxf(fmaxf(fabsf(v.x), fabsf(v.y)), fmaxf(fabsf(v.z), fabsf(v.w)));
    }
    __shared__ float red[256];
    red[threadIdx.x] = amax;
    __syncthreads();
    for (int s = 128; s; s >>= 1) {
        if (threadIdx.x < s) red[threadIdx.x] = fmaxf(red[threadIdx.x], red[threadIdx.x + s]);
        __syncthreads();
    }
    float scale = fmaxf(red[0], 1e-5f) / 127.0f;
    if (threadIdx.x == 0) scales[row] = scale;

    {
        int i = threadIdx.x * 4;
        float4 v = *(const float4*)(r + i);
        char4 o;
        o.x = (signed char)(int)fminf(127.f, fmaxf(-128.f, rintf(v.x / scale)));
        o.y = (signed char)(int)fminf(127.f, fmaxf(-128.f, rintf(v.y / scale)));
        o.z = (signed char)(int)fminf(127.f, fmaxf(-128.f, rintf(v.z / scale)));
        o.w = (signed char)(int)fminf(127.f, fmaxf(-128.f, rintf(v.w / scale)));
        *(char4*)(q + (size_t)row * DIN + i) = o;
    }
}

// b1 is quantized as ONE channel over its last (only) dim of 4096.
__global__ void quant_bias_kernel(const float* __restrict__ b1) {
    __shared__ float red[256];
    float amax = 0.f;
    for (int i = threadIdx.x; i < HID; i += 256) amax = fmaxf(amax, fabsf(b1[i]));
    red[threadIdx.x] = amax;
    __syncthreads();
    for (int s = 128; s; s >>= 1) {
        if (threadIdx.x < s) red[threadIdx.x] = fmaxf(red[threadIdx.x], red[threadIdx.x + s]);
        __syncthreads();
    }
    float scale = fmaxf(red[0], 1e-5f) / 127.0f;
    for (int i = threadIdx.x; i < HID; i += 256) {
        float qv = fminf(127.f, fmaxf(-128.f, rintf(b1[i] / scale)));
        g_qb[i] = qv * scale;
    }
}

// ---------------- topk predictor: count positives of (x[:, :103] @ W1[:, :103]^T + b1)
__global__ void __launch_bounds__(256, 2)
topk_count_kernel(const float* __restrict__ x, const float* __restrict__ W1,
                  const float* __restrict__ b1) {
    __shared__ __align__(16) float As[BK][BM];
    __shared__ __align__(16) float Bs[BK][BN];
    __shared__ int cnt[BN];

    int tid = threadIdx.x;
    int ty = tid >> 4, tx = tid & 15;
    int i0 = blockIdx.y * BM, h0 = blockIdx.x * BN;

    float acc[8][4];
#pragma unroll
    for (int m = 0; m < 8; m++)
#pragma unroll
        for (int n = 0; n < 4; n++) acc[m][n] = 0.f;

    for (int k0 = 0; k0 < 112; k0 += BK) {  // 112 = ceil16(103)
#pragma unroll
        for (int l = 0; l < 2; l++) {
            int idx = tid + l * 256, rr = idx >> 2, c4 = idx & 3;
            float4 v = *(const float4*)(x + (size_t)(i0 + rr) * DIN + k0 + c4 * 4);
            int kb = k0 + c4 * 4;
            if (kb + 0 >= TOPKC) v.x = 0.f;
            if (kb + 1 >= TOPKC) v.y = 0.f;
            if (kb + 2 >= TOPKC) v.z = 0.f;
            if (kb + 3 >= TOPKC) v.w = 0.f;
            As[c4 * 4 + 0][rr] = v.x; As[c4 * 4 + 1][rr] = v.y;
            As[c4 * 4 + 2][rr] = v.z; As[c4 * 4 + 3][rr] = v.w;
        }
        {
            int rr = tid >> 2, c4 = tid & 3;
            float4 v = *(const float4*)(W1 + (size_t)(h0 + rr) * DIN + k0 + c4 * 4);
            int kb = k0 + c4 * 4;
            if (kb + 0 >= TOPKC) v.x = 0.f;
            if (kb + 1 >= TOPKC) v.y = 0.f;
            if (kb + 2 >= TOPKC) v.z = 0.f;
            if (kb + 3 >= TOPKC) v.w = 0.f;
            Bs[c4 * 4 + 0][rr] = v.x; Bs[c4 * 4 + 1][rr] = v.y;
            Bs[c4 * 4 + 2][rr] = v.z; Bs[c4 * 4 + 3][rr] = v.w;
        }
        __syncthreads();
#pragma unroll
        for (int kk = 0; kk < BK; kk++) {
            float4 a0 = *(const float4*)&As[kk][ty * 8];
            float4 a1 = *(const float4*)&As[kk][ty * 8 + 4];
            float4 b  = *(const float4*)&Bs[kk][tx * 4];
            float av[8] = {a0.x, a0.y, a0.z, a0.w, a1.x, a1.y, a1.z, a1.w};
            float bv[4] = {b.x, b.y, b.z, b.w};
#pragma unroll
            for (int m = 0; m < 8; m++)
#pragma unroll
                for (int n = 0; n < 4; n++) acc[m][n] += av[m] * bv[n];
        }
        __syncthreads();
    }

    if (tid < BN) cnt[tid] = 0;
    __syncthreads();
#pragma unroll
    for (int n = 0; n < 4; n++) {
        float bv = b1[h0 + tx * 4 + n];
        int c = 0;
#pragma unroll
        for (int m = 0; m < 8; m++)
            if (acc[m][n] + bv > 0.f) c++;
        atomicAdd(&cnt[tx * 4 + n], c);
    }
    __syncthreads();
    if (tid < BN) atomicAdd(&g_counts[h0 + tid], cnt[tid]);
}

// ---------------- main fused GEMM: fp32 prod + int8(dp4a) q_pre -> select -> gelu -> g_h
__device__ __forceinline__ float gelu_exact(float v) {
    return 0.5f * v * (1.0f + erff(v * 0.70710678118654752440f));
}

__global__ void __launch_bounds__(256, 2)
mlp1_kernel(const float* __restrict__ x, const float* __restrict__ W1,
            const float* __restrict__ b1) {
    __shared__ __align__(16) float As[BK][BM];
    __shared__ __align__(16) float Bs[BK][BN];
    __shared__ __align__(16) int QA[4][BM];
    __shared__ __align__(16) int QB[4][BN];

    int tid = threadIdx.x;
    int ty = tid >> 4, tx = tid & 15;
    int i0 = blockIdx.y * BM, h0 = blockIdx.x * BN;

    float accf[8][4];
    int   acci[8][4];
#pragma unroll
    for (int m = 0; m < 8; m++)
#pragma unroll
        for (int n = 0; n < 4; n++) { accf[m][n] = 0.f; acci[m][n] = 0; }

    const int* qx4 = (const int*)g_qx;
    const int* qw4 = (const int*)g_qw;

    for (int k0 = 0; k0 < DIN; k0 += BK) {
#pragma unroll
        for (int l = 0; l < 2; l++) {
            int idx = tid + l * 256, rr = idx >> 2, c4 = idx & 3;
            float4 v = *(const float4*)(x + (size_t)(i0 + rr) * DIN + k0 + c4 * 4);
            As[c4 * 4 + 0][rr] = v.x; As[c4 * 4 + 1][rr] = v.y;
            As[c4 * 4 + 2][rr] = v.z; As[c4 * 4 + 3][rr] = v.w;
            QA[c4][rr] = qx4[(size_t)(i0 + rr) * (DIN / 4) + (k0 >> 2) + c4];
        }
        {
            int rr = tid >> 2, c4 = tid & 3;
            float4 v = *(const float4*)(W1 + (size_t)(h0 + rr) * DIN + k0 + c4 * 4);
            Bs[c4 * 4 + 0][rr] = v.x; Bs[c4 * 4 + 1][rr] = v.y;
            Bs[c4 * 4 + 2][rr] = v.z; Bs[c4 * 4 + 3][rr] = v.w;
            QB[c4][rr] = qw4[(size_t)(h0 + rr) * (DIN / 4) + (k0 >> 2) + c4];
        }
        __syncthreads();

#pragma unroll
        for (int kk = 0; kk < BK; kk++) {
            float4 a0 = *(const float4*)&As[kk][ty * 8];
            float4 a1 = *(const float4*)&As[kk][ty * 8 + 4];
            float4 b  = *(const float4*)&Bs[kk][tx * 4];
            float av[8] = {a0.x, a0.y, a0.z, a0.w, a1.x, a1.y, a1.z, a1.w};
            float bv[4] = {b.x, b.y, b.z, b.w};
#pragma unroll
            for (int m = 0; m < 8; m++)
#pragma unroll
                for (int n = 0; n < 4; n++) accf[m][n] += av[m] * bv[n];
        }
#pragma unroll
        for (int g4 = 0; g4 < 4; g4++) {
            int4 qa0 = *(const int4*)&QA[g4][ty * 8];
            int4 qa1 = *(const int4*)&QA[g4][ty * 8 + 4];
            int4 qb  = *(const int4*)&QB[g4][tx * 4];
            int qav[8] = {qa0.x, qa0.y, qa0.z, qa0.w, qa1.x, qa1.y, qa1.z, qa1.w};
            int qbv[4] = {qb.x, qb.y, qb.z, qb.w};
#pragma unroll
            for (int m = 0; m < 8; m++)
#pragma unroll
                for (int n = 0; n < 4; n++) acci[m][n] = __dp4a(qav[m], qbv[n], acci[m][n]);
        }
        __syncthreads();
    }

    // epilogue: channel select + exact gelu, vectorized float4 store
    float b1v[4], swv[4], qbv[4];
    bool fsel[4];
#pragma unroll
    for (int n = 0; n < 4; n++) {
        int h = h0 + tx * 4 + n;
        b1v[n] = b1[h];
        swv[n] = g_sw[h];
        qbv[n] = g_qb[h];
        fsel[n] = g_counts[h] > THRESH;
    }
#pragma unroll
    for (int m = 0; m < 8; m++) {
        int i = i0 + ty * 8 + m;
        float sxv = g_sx[i];
        float vals[4];
#pragma unroll
        for (int n = 0; n < 4; n++) {
            float v = fsel[n] ? (accf[m][n] + b1v[n])
                              : fmaf(sxv * swv[n], (float)acci[m][n], qbv[n]);
            vals[n] = gelu_exact(v);
        }
        float4 o = make_float4(vals[0], vals[1], vals[2], vals[3]);
        *(float4*)&g_h[(size_t)i * HID + h0 + tx * 4] = o;
    }
}

// ---------------- second layer: out = g_h @ W2^T + b2 -----------------------
__global__ void __launch_bounds__(256, 2)
mlp2_kernel(const float* __restrict__ W2, const float* __restrict__ b2,
            float* __restrict__ out) {
    __shared__ __align__(16) float As[BK][BM];
    __shared__ __align__(16) float Bs[BK][BN];

    int tid = threadIdx.x;
    int ty = tid >> 4, tx = tid & 15;
    int i0 = blockIdx.y * BM, d0 = blockIdx.x * BN;

    float acc[8][4];
#pragma unroll
    for (int m = 0; m < 8; m++)
#pragma unroll
        for (int n = 0; n < 4; n++) acc[m][n] = 0.f;

    for (int k0 = 0; k0 < HID; k0 += BK) {
#pragma unroll
        for (int l = 0; l < 2; l++) {
            int idx = tid + l * 256, rr = idx >> 2, c4 = idx & 3;
            float4 v = *(const float4*)&g_h[(size_t)(i0 + rr) * HID + k0 + c4 * 4];
            As[c4 * 4 + 0][rr] = v.x; As[c4 * 4 + 1][rr] = v.y;
            As[c4 * 4 + 2][rr] = v.z; As[c4 * 4 + 3][rr] = v.w;
        }
        {
            int rr = tid >> 2, c4 = tid & 3;
            float4 v = *(const float4*)(W2 + (size_t)(d0 + rr) * HID + k0 + c4 * 4);
            Bs[c4 * 4 + 0][rr] = v.x; Bs[c4 * 4 + 1][rr] = v.y;
            Bs[c4 * 4 + 2][rr] = v.z; Bs[c4 * 4 + 3][rr] = v.w;
        }
        __syncthreads();
#pragma unroll
        for (int kk = 0; kk < BK; kk++) {
            float4 a0 = *(const float4*)&As[kk][ty * 8];
            float4 a1 = *(const float4*)&As[kk][ty * 8 + 4];
            float4 b  = *(const float4*)&Bs[kk][tx * 4];
            float av[8] = {a0.x, a0.y, a0.z, a0.w, a1.x, a1.y, a1.z, a1.w};
            float bv[4] = {b.x, b.y, b.z, b.w};
#pragma unroll
            for (int m = 0; m < 8; m++)
#pragma unroll
                for (int n = 0; n < 4; n++) acc[m][n] += av[m] * bv[n];
        }
        __syncthreads();
    }

    float4 bb = *(const float4*)(b2 + d0 + tx * 4);
    float bv[4] = {bb.x, bb.y, bb.z, bb.w};
#pragma unroll
    for (int m = 0; m < 8; m++) {
        int i = i0 + ty * 8 + m;
        float4 o = make_float4(acc[m][0] + bv[0], acc[m][1] + bv[1],
                               acc[m][2] + bv[2], acc[m][3] + bv[3]);
        *(float4*)(out + (size_t)i * DIN + d0 + tx * 4) = o;
    }
}

// ---------------- launch -----------------------------------------------------
extern "C" void kernel_launch(void* const* d_in, const int* in_sizes, int n_in,
                              void* d_out, int out_size) {
    const float* x  = (const float*)d_in[0];   // [4,2048,1024] -> [8192,1024]
    const float* W1 = (const float*)d_in[1];   // [4096,1024]
    const float* b1 = (const float*)d_in[2];   // [4096]
    const float* W2 = (const float*)d_in[3];   // [1024,4096]
    const float* b2 = (const float*)d_in[4];   // [1024]
    float* out = (float*)d_out;                // [8192,1024]

    zero_counts_kernel<<<HID / 256, 256>>>();
    quant_rows_kernel<<<NTOK, 256>>>(x, 0);
    quant_rows_kernel<<<HID, 256>>>(W1, 1);
    quant_bias_kernel<<<1, 256>>>(b1);

    dim3 g1(HID / BN, NTOK / BM);   // (64, 64)
    topk_count_kernel<<<g1, 256>>>(x, W1, b1);
    mlp1_kernel<<<g1, 256>>>(x, W1, b1);

    dim3 g2(DIN / BN, NTOK / BM);   // (16, 64)
    mlp2_kernel<<<g2, 256>>>(W2, b2, out);
}

// round 5
// speedup vs baseline: 1.3290x; 1.3285x over previous
#include <cuda_runtime.h>
#include <cuda_bf16.h>
#include <math.h>
#include <stdint.h>

#define NTOK 8192
#define DIN  1024
#define HID  4096
#define TOPKC 103
#define THRESH 2048

#define BM 128
#define BN 64
#define BK 16

typedef __nv_bfloat16 bf16;

// ---------------- scratch ----------------------------------------------------
__device__ __align__(16) signed char g_qx[(size_t)NTOK * DIN];
__device__ __align__(16) signed char g_qw[(size_t)HID * DIN];
__device__ float g_sx[NTOK];
__device__ float g_sw[HID];
__device__ float g_qb[HID];
__device__ int   g_counts[HID];
__device__ __align__(16) bf16 g_hhi[(size_t)NTOK * HID];
__device__ __align__(16) bf16 g_hlo[(size_t)NTOK * HID];
__device__ __align__(16) bf16 g_w2hi[(size_t)DIN * HID];
__device__ __align__(16) bf16 g_w2lo[(size_t)DIN * HID];

// ---------------- small helpers ----------------------------------------------
__device__ __forceinline__ uint32_t smem_u32(const void* p) {
    uint32_t a;
    asm("{ .reg .u64 t; cvta.to.shared.u64 t, %1; cvt.u32.u64 %0, t; }" : "=r"(a) : "l"(p));
    return a;
}
__device__ __forceinline__ void cpa(uint32_t s, const void* g) {
    asm volatile("cp.async.cg.shared.global [%0], [%1], 16;" :: "r"(s), "l"(g));
}
#define CP_COMMIT() asm volatile("cp.async.commit_group;" ::: "memory")
#define CP_WAIT(N)  asm volatile("cp.async.wait_group %0;" :: "n"(N) : "memory")

__device__ __forceinline__ void ldsm4(uint32_t* r, uint32_t addr) {
    asm volatile("ldmatrix.sync.aligned.m8n8.x4.shared.b16 {%0,%1,%2,%3}, [%4];"
        : "=r"(r[0]), "=r"(r[1]), "=r"(r[2]), "=r"(r[3]) : "r"(addr));
}
__device__ __forceinline__ void mma_bf16(float* c, const uint32_t* a, const uint32_t* b) {
    asm volatile("mma.sync.aligned.m16n8k16.row.col.f32.bf16.bf16.f32 "
        "{%0,%1,%2,%3}, {%4,%5,%6,%7}, {%8,%9}, {%0,%1,%2,%3};"
        : "+f"(c[0]), "+f"(c[1]), "+f"(c[2]), "+f"(c[3])
        : "r"(a[0]), "r"(a[1]), "r"(a[2]), "r"(a[3]), "r"(b[0]), "r"(b[1]));
}
__device__ __forceinline__ float gelu_exact(float v) {
    return 0.5f * v * (1.0f + erff(v * 0.70710678118654752440f));
}

// ================= scalar prep / topk / mlp1 (proven in R1) ====================
__global__ void quant_rows_kernel(const float* __restrict__ src, int which) {
    float* scales = which ? g_sw : g_sx;
    signed char* q = which ? g_qw : g_qx;
    int row = blockIdx.x;
    const float* r = src + (size_t)row * DIN;
    float4 v = ((const float4*)r)[threadIdx.x];
    float amax = fmaxf(fmaxf(fabsf(v.x), fabsf(v.y)), fmaxf(fabsf(v.z), fabsf(v.w)));
    __shared__ float red[256];
    red[threadIdx.x] = amax; __syncthreads();
    for (int s = 128; s; s >>= 1) {
        if (threadIdx.x < s) red[threadIdx.x] = fmaxf(red[threadIdx.x], red[threadIdx.x + s]);
        __syncthreads();
    }
    float scale = fmaxf(red[0], 1e-5f) / 127.0f;
    if (threadIdx.x == 0) scales[row] = scale;
    char4 o;
    o.x = (signed char)(int)fminf(127.f, fmaxf(-128.f, rintf(v.x / scale)));
    o.y = (signed char)(int)fminf(127.f, fmaxf(-128.f, rintf(v.y / scale)));
    o.z = (signed char)(int)fminf(127.f, fmaxf(-128.f, rintf(v.z / scale)));
    o.w = (signed char)(int)fminf(127.f, fmaxf(-128.f, rintf(v.w / scale)));
    *(char4*)(q + (size_t)row * DIN + threadIdx.x * 4) = o;
}

__global__ void quant_bias_kernel(const float* __restrict__ b1) {
    __shared__ float red[256];
    int tid = threadIdx.x;
    float amax = 0.f;
    for (int i = tid; i < HID; i += 256) amax = fmaxf(amax, fabsf(b1[i]));
    red[tid] = amax; __syncthreads();
    for (int s = 128; s; s >>= 1) {
        if (tid < s) red[tid] = fmaxf(red[tid], red[tid + s]);
        __syncthreads();
    }
    float scale = fmaxf(red[0], 1e-5f) / 127.0f;
    for (int i = tid; i < HID; i += 256) {
        g_qb[i] = fminf(127.f, fmaxf(-128.f, rintf(b1[i] / scale))) * scale;
        g_counts[i] = 0;
    }
}

__global__ void __launch_bounds__(256, 2)
topk_count_kernel(const float* __restrict__ x, const float* __restrict__ W1,
                  const float* __restrict__ b1) {
    __shared__ __align__(16) float As[BK][BM];
    __shared__ __align__(16) float Bs[BK][BN];
    __shared__ int cnt[BN];
    int tid = threadIdx.x;
    int ty = tid >> 4, tx = tid & 15;
    int i0 = blockIdx.y * BM, h0 = blockIdx.x * BN;
    float acc[8][4];
#pragma unroll
    for (int m = 0; m < 8; m++)
#pragma unroll
        for (int n = 0; n < 4; n++) acc[m][n] = 0.f;

    for (int k0 = 0; k0 < 112; k0 += BK) {
#pragma unroll
        for (int l = 0; l < 2; l++) {
            int idx = tid + l * 256, rr = idx >> 2, c4 = idx & 3;
            float4 v = *(const float4*)(x + (size_t)(i0 + rr) * DIN + k0 + c4 * 4);
            int kb = k0 + c4 * 4;
            if (kb + 0 >= TOPKC) v.x = 0.f;
            if (kb + 1 >= TOPKC) v.y = 0.f;
            if (kb + 2 >= TOPKC) v.z = 0.f;
            if (kb + 3 >= TOPKC) v.w = 0.f;
            As[c4*4+0][rr] = v.x; As[c4*4+1][rr] = v.y;
            As[c4*4+2][rr] = v.z; As[c4*4+3][rr] = v.w;
        }
        {
            int rr = tid >> 2, c4 = tid & 3;
            float4 v = *(const float4*)(W1 + (size_t)(h0 + rr) * DIN + k0 + c4 * 4);
            int kb = k0 + c4 * 4;
            if (kb + 0 >= TOPKC) v.x = 0.f;
            if (kb + 1 >= TOPKC) v.y = 0.f;
            if (kb + 2 >= TOPKC) v.z = 0.f;
            if (kb + 3 >= TOPKC) v.w = 0.f;
            Bs[c4*4+0][rr] = v.x; Bs[c4*4+1][rr] = v.y;
            Bs[c4*4+2][rr] = v.z; Bs[c4*4+3][rr] = v.w;
        }
        __syncthreads();
#pragma unroll
        for (int kk = 0; kk < BK; kk++) {
            float4 a0 = *(const float4*)&As[kk][ty * 8];
            float4 a1 = *(const float4*)&As[kk][ty * 8 + 4];
            float4 b  = *(const float4*)&Bs[kk][tx * 4];
            float av[8] = {a0.x, a0.y, a0.z, a0.w, a1.x, a1.y, a1.z, a1.w};
            float bv[4] = {b.x, b.y, b.z, b.w};
#pragma unroll
            for (int m = 0; m < 8; m++)
#pragma unroll
                for (int n = 0; n < 4; n++) acc[m][n] += av[m] * bv[n];
        }
        __syncthreads();
    }
    if (tid < BN) cnt[tid] = 0;
    __syncthreads();
#pragma unroll
    for (int n = 0; n < 4; n++) {
        float bv = b1[h0 + tx * 4 + n];
        int c = 0;
#pragma unroll
        for (int m = 0; m < 8; m++)
            if (acc[m][n] + bv > 0.f) c++;
        atomicAdd(&cnt[tx * 4 + n], c);
    }
    __syncthreads();
    if (tid < BN) atomicAdd(&g_counts[h0 + tid], cnt[tid]);
}

__global__ void __launch_bounds__(256, 2)
mlp1_kernel(const float* __restrict__ x, const float* __restrict__ W1,
            const float* __restrict__ b1) {
    __shared__ __align__(16) float As[BK][BM];
    __shared__ __align__(16) float Bs[BK][BN];
    __shared__ __align__(16) int QA[4][BM];
    __shared__ __align__(16) int QB[4][BN];
    int tid = threadIdx.x;
    int ty = tid >> 4, tx = tid & 15;
    int i0 = blockIdx.y * BM, h0 = blockIdx.x * BN;
    float accf[8][4];
    int   acci[8][4];
#pragma unroll
    for (int m = 0; m < 8; m++)
#pragma unroll
        for (int n = 0; n < 4; n++) { accf[m][n] = 0.f; acci[m][n] = 0; }

    const int* qx4 = (const int*)g_qx;
    const int* qw4 = (const int*)g_qw;

    for (int k0 = 0; k0 < DIN; k0 += BK) {
#pragma unroll
        for (int l = 0; l < 2; l++) {
            int idx = tid + l * 256, rr = idx >> 2, c4 = idx & 3;
            float4 v = *(const float4*)(x + (size_t)(i0 + rr) * DIN + k0 + c4 * 4);
            As[c4*4+0][rr] = v.x; As[c4*4+1][rr] = v.y;
            As[c4*4+2][rr] = v.z; As[c4*4+3][rr] = v.w;
            QA[c4][rr] = qx4[(size_t)(i0 + rr) * (DIN/4) + (k0 >> 2) + c4];
        }
        {
            int rr = tid >> 2, c4 = tid & 3;
            float4 v = *(const float4*)(W1 + (size_t)(h0 + rr) * DIN + k0 + c4 * 4);
            Bs[c4*4+0][rr] = v.x; Bs[c4*4+1][rr] = v.y;
            Bs[c4*4+2][rr] = v.z; Bs[c4*4+3][rr] = v.w;
            QB[c4][rr] = qw4[(size_t)(h0 + rr) * (DIN/4) + (k0 >> 2) + c4];
        }
        __syncthreads();
#pragma unroll
        for (int kk = 0; kk < BK; kk++) {
            float4 a0 = *(const float4*)&As[kk][ty * 8];
            float4 a1 = *(const float4*)&As[kk][ty * 8 + 4];
            float4 b  = *(const float4*)&Bs[kk][tx * 4];
            float av[8] = {a0.x, a0.y, a0.z, a0.w, a1.x, a1.y, a1.z, a1.w};
            float bv[4] = {b.x, b.y, b.z, b.w};
#pragma unroll
            for (int m = 0; m < 8; m++)
#pragma unroll
                for (int n = 0; n < 4; n++) accf[m][n] += av[m] * bv[n];
        }
#pragma unroll
        for (int g4 = 0; g4 < 4; g4++) {
            int4 qa0 = *(const int4*)&QA[g4][ty * 8];
            int4 qa1 = *(const int4*)&QA[g4][ty * 8 + 4];
            int4 qb  = *(const int4*)&QB[g4][tx * 4];
            int qav[8] = {qa0.x, qa0.y, qa0.z, qa0.w, qa1.x, qa1.y, qa1.z, qa1.w};
            int qbv[4] = {qb.x, qb.y, qb.z, qb.w};
#pragma unroll
            for (int m = 0; m < 8; m++)
#pragma unroll
                for (int n = 0; n < 4; n++) acci[m][n] = __dp4a(qav[m], qbv[n], acci[m][n]);
        }
        __syncthreads();
    }

    float b1v[4], swv[4], qbv[4];
    bool fsel[4];
#pragma unroll
    for (int n = 0; n < 4; n++) {
        int h = h0 + tx * 4 + n;
        b1v[n] = b1[h]; swv[n] = g_sw[h]; qbv[n] = g_qb[h];
        fsel[n] = g_counts[h] > THRESH;
    }
#pragma unroll
    for (int m = 0; m < 8; m++) {
        int i = i0 + ty * 8 + m;
        float sxv = g_sx[i];
        float vals[4];
#pragma unroll
        for (int n = 0; n < 4; n++) {
            float v = fsel[n] ? (accf[m][n] + b1v[n])
                              : fmaf(sxv * swv[n], (float)acci[m][n], qbv[n]);
            vals[n] = gelu_exact(v);
        }
        // split h into bf16 hi/lo pairs for the HMMA second layer
        __nv_bfloat162 h2[2], l2[2];
#pragma unroll
        for (int k = 0; k < 4; k++) {
            bf16 hb = __float2bfloat16(vals[k]);
            bf16 lb = __float2bfloat16(vals[k] - __bfloat162float(hb));
            if (k & 1) { h2[k>>1].y = hb; l2[k>>1].y = lb; }
            else       { h2[k>>1].x = hb; l2[k>>1].x = lb; }
        }
        size_t o = (size_t)i * HID + h0 + tx * 4;
        *(uint2*)(g_hhi + o) = make_uint2(*(uint32_t*)&h2[0], *(uint32_t*)&h2[1]);
        *(uint2*)(g_hlo + o) = make_uint2(*(uint32_t*)&l2[0], *(uint32_t*)&l2[1]);
    }
}

__global__ void prep_w2_kernel(const float* __restrict__ W2) {
    int row = blockIdx.x, tid = threadIdx.x;
    const float4* r = (const float4*)(W2 + (size_t)row * HID);
#pragma unroll
    for (int j = 0; j < 4; j++) {
        float4 v = r[tid + 256 * j];
        float e[4] = {v.x, v.y, v.z, v.w};
        __nv_bfloat162 h2[2], l2[2];
#pragma unroll
        for (int k = 0; k < 4; k++) {
            bf16 hb = __float2bfloat16(e[k]);
            bf16 lb = __float2bfloat16(e[k] - __bfloat162float(hb));
            if (k & 1) { h2[k>>1].y = hb; l2[k>>1].y = lb; }
            else       { h2[k>>1].x = hb; l2[k>>1].x = lb; }
        }
        size_t o = (size_t)row * HID + (tid + 256 * j) * 4;
        *(uint2*)(g_w2hi + o) = make_uint2(*(uint32_t*)&h2[0], *(uint32_t*)&h2[1]);
        *(uint2*)(g_w2lo + o) = make_uint2(*(uint32_t*)&l2[0], *(uint32_t*)&l2[1]);
    }
}

// ================= HMMA G2: out = h @ W2^T + b2 (padded 144B rows, no swizzle)
// CTA 128(M) x 128(N), 8 warps (4m x 2n), warp tile 32x64, BK=64, 2-stage cp.async
#define ROWB 144   // 128 data bytes + 16 pad
__global__ void __launch_bounds__(256, 1)
g2_kernel(const float* __restrict__ b2, float* __restrict__ out) {
    extern __shared__ char dsm[];
    uint32_t sbase = (smem_u32(dsm) + 127u) & ~127u;
    const int i0 = blockIdx.y * 128, d0 = blockIdx.x * 128;
    const int tid = threadIdx.x, w = tid >> 5, lane = tid & 31;
    const int wm = w & 3, wn = w >> 2;
    const int NT = HID / 64;
    const int BUF = 128 * ROWB;      // 18432
    const int STG = 4 * BUF;         // 73728: Ahi, Alo, Bhi, Blo

    auto load_tile = [&](int kt, int st) {
        uint32_t sb = sbase + st * STG;
#pragma unroll
        for (int c = 0; c < 4; c++) {
            int idx = tid + c * 256, row = idx >> 3, c16 = idx & 7;
            uint32_t so = (uint32_t)(row * ROWB + c16 * 16);
            size_t ga = (size_t)(i0 + row) * HID + kt * 64 + c16 * 8;
            size_t gb = (size_t)(d0 + row) * HID + kt * 64 + c16 * 8;
            cpa(sb + 0 * BUF + so, g_hhi  + ga);
            cpa(sb + 1 * BUF + so, g_hlo  + ga);
            cpa(sb + 2 * BUF + so, g_w2hi + gb);
            cpa(sb + 3 * BUF + so, g_w2lo + gb);
        }
        CP_COMMIT();
    };

    uint32_t aRow[2], bRow[4];
#pragma unroll
    for (int mt = 0; mt < 2; mt++)
        aRow[mt] = (uint32_t)((wm * 32 + mt * 16 + (lane & 15)) * ROWB);
#pragma unroll
    for (int p = 0; p < 4; p++)
        bRow[p] = (uint32_t)((wn * 64 + p * 16 + ((lane >> 4) << 3) + (lane & 7)) * ROWB);
    uint32_t aK = (uint32_t)((lane >> 4) * 16);
    uint32_t bK = (uint32_t)(((lane >> 3) & 1) * 16);

    float acc[2][8][4];
#pragma unroll
    for (int mt = 0; mt < 2; mt++)
#pragma unroll
        for (int nt = 0; nt < 8; nt++)
#pragma unroll
            for (int r = 0; r < 4; r++) acc[mt][nt][r] = 0.f;

    load_tile(0, 0);
    load_tile(1, 1);
    for (int kt = 0; kt < NT; kt++) {
        int st = kt & 1;
        if (kt + 2 < NT) CP_WAIT(1); else CP_WAIT(0);
        __syncthreads();
        uint32_t sb = sbase + st * STG;
#pragma unroll
        for (int kk = 0; kk < 4; kk++) {
            uint32_t ka = aK + kk * 32;
            uint32_t kb = bK + kk * 32;
            uint32_t ah[2][4], al[2][4];
#pragma unroll
            for (int mt = 0; mt < 2; mt++) {
                ldsm4(ah[mt], sb + 0 * BUF + aRow[mt] + ka);
                ldsm4(al[mt], sb + 1 * BUF + aRow[mt] + ka);
            }
            uint32_t bh[8][2], bl[8][2];
#pragma unroll
            for (int p = 0; p < 4; p++) {
                uint32_t t[4];
                ldsm4(t, sb + 2 * BUF + bRow[p] + kb);
                bh[2*p][0]=t[0]; bh[2*p][1]=t[1]; bh[2*p+1][0]=t[2]; bh[2*p+1][1]=t[3];
                ldsm4(t, sb + 3 * BUF + bRow[p] + kb);
                bl[2*p][0]=t[0]; bl[2*p][1]=t[1]; bl[2*p+1][0]=t[2]; bl[2*p+1][1]=t[3];
            }
#pragma unroll
            for (int mt = 0; mt < 2; mt++)
#pragma unroll
                for (int nt = 0; nt < 8; nt++) {
                    mma_bf16(acc[mt][nt], ah[mt], bh[nt]);
                    mma_bf16(acc[mt][nt], ah[mt], bl[nt]);
                    mma_bf16(acc[mt][nt], al[mt], bh[nt]);
                }
        }
        __syncthreads();
        if (kt + 2 < NT) load_tile(kt + 2, st);
    }

    __shared__ float sbb[128];
    if (tid < 128) sbb[tid] = b2[d0 + tid];
    __syncthreads();

    int gq = lane >> 2, q4 = lane & 3;
#pragma unroll
    for (int mt = 0; mt < 2; mt++)
#pragma unroll
        for (int half = 0; half < 2; half++) {
            int rl = wm * 32 + mt * 16 + gq + half * 8;
            float* dst = out + (size_t)(i0 + rl) * DIN + d0;
#pragma unroll
            for (int nt = 0; nt < 8; nt++) {
                int cl = wn * 64 + nt * 8 + q4 * 2;
                float2 o = make_float2(acc[mt][nt][half*2+0] + sbb[cl],
                                       acc[mt][nt][half*2+1] + sbb[cl+1]);
                *(float2*)(dst + cl) = o;
            }
        }
}

// ---------------- launch --------------------------------------------------------
extern "C" void kernel_launch(void* const* d_in, const int* in_sizes, int n_in,
                              void* d_out, int out_size) {
    const float* x  = (const float*)d_in[0];
    const float* W1 = (const float*)d_in[1];
    const float* b1 = (const float*)d_in[2];
    const float* W2 = (const float*)d_in[3];
    const float* b2 = (const float*)d_in[4];
    float* out = (float*)d_out;

    const int SM_G2 = 2 * 4 * 128 * ROWB + 256;   // 147712
    cudaFuncSetAttribute(g2_kernel, cudaFuncAttributeMaxDynamicSharedMemorySize, SM_G2);

    quant_bias_kernel<<<1, 256>>>(b1);            // also zeroes g_counts
    quant_rows_kernel<<<NTOK, 256>>>(x, 0);
    quant_rows_kernel<<<HID, 256>>>(W1, 1);
    prep_w2_kernel<<<DIN, 256>>>(W2);

    dim3 g1(HID / BN, NTOK / BM);   // (64, 64)
    topk_count_kernel<<<g1, 256>>>(x, W1, b1);
    mlp1_kernel<<<g1, 256>>>(x, W1, b1);

    dim3 gg2(DIN / 128, NTOK / 128); // (8, 64)
    g2_kernel<<<gg2, 256, SM_G2>>>(b2, out);
}

// round 7
// speedup vs baseline: 2.4768x; 1.8636x over previous
#include <cuda_runtime.h>
#include <cuda_bf16.h>
#include <math.h>
#include <stdint.h>

#define NTOK 8192
#define DIN  1024
#define HID  4096
#define TOPKC 103
#define KTP  128
#define THRESH 2048

typedef __nv_bfloat16 bf16;

// ---------------- scratch ----------------------------------------------------
__device__ __align__(16) bf16 g_xhi[(size_t)NTOK*DIN];
__device__ __align__(16) bf16 g_xlo[(size_t)NTOK*DIN];
__device__ __align__(16) bf16 g_xq [(size_t)NTOK*DIN];
__device__ __align__(16) bf16 g_whi[(size_t)HID*DIN];
__device__ __align__(16) bf16 g_wlo[(size_t)HID*DIN];
__device__ __align__(16) bf16 g_wq [(size_t)HID*DIN];
__device__ __align__(16) bf16 g_xthi[(size_t)NTOK*KTP];
__device__ __align__(16) bf16 g_xtlo[(size_t)NTOK*KTP];
__device__ __align__(16) bf16 g_wthi[(size_t)HID*KTP];
__device__ __align__(16) bf16 g_wtlo[(size_t)HID*KTP];
__device__ __align__(16) bf16 g_w2hi[(size_t)DIN*HID];
__device__ __align__(16) bf16 g_w2lo[(size_t)DIN*HID];
__device__ __align__(16) bf16 g_hhi[(size_t)NTOK*HID];
__device__ __align__(16) bf16 g_hlo[(size_t)NTOK*HID];
__device__ float g_sx[NTOK];
__device__ float g_sw[HID];
__device__ float g_qb[HID];
__device__ int   g_counts[HID];

// ---------------- helpers ------------------------------------------------------
__device__ __forceinline__ uint32_t smem_u32(const void* p) {
    uint32_t a;
    asm("{ .reg .u64 t; cvta.to.shared.u64 t, %1; cvt.u32.u64 %0, t; }" : "=r"(a) : "l"(p));
    return a;
}
__device__ __forceinline__ void cpa(uint32_t s, const void* g) {
    asm volatile("cp.async.cg.shared.global [%0], [%1], 16;" :: "r"(s), "l"(g));
}
#define CP_COMMIT() asm volatile("cp.async.commit_group;" ::: "memory")
#define CP_WAIT(N)  asm volatile("cp.async.wait_group %0;" :: "n"(N) : "memory")

__device__ __forceinline__ void ldsm4(uint32_t* r, uint32_t addr) {
    asm volatile("ldmatrix.sync.aligned.m8n8.x4.shared.b16 {%0,%1,%2,%3}, [%4];"
        : "=r"(r[0]), "=r"(r[1]), "=r"(r[2]), "=r"(r[3]) : "r"(addr));
}
__device__ __forceinline__ void mma_bf16(float* c, const uint32_t* a, const uint32_t* b) {
    asm volatile("mma.sync.aligned.m16n8k16.row.col.f32.bf16.bf16.f32 "
        "{%0,%1,%2,%3}, {%4,%5,%6,%7}, {%8,%9}, {%0,%1,%2,%3};"
        : "+f"(c[0]), "+f"(c[1]), "+f"(c[2]), "+f"(c[3])
        : "r"(a[0]), "r"(a[1]), "r"(a[2]), "r"(a[3]), "r"(b[0]), "r"(b[1]));
}
__device__ __forceinline__ float gelu_exact(float v) {
    return 0.5f * v * (1.0f + erff(v * 0.70710678118654752440f));
}

#define ROWB 144
#define BUF  (128 * ROWB)      // 18432 (BK=64 tiles: topk, g2)
#define ROWB32 80
#define BUF32  (128 * ROWB32)  // 10240 (BK=32 tiles: g1)

// ================= G1: HMMA fused fp-split + exact-q, select, gelu, split h ====
// CTA 128(M) x 128(N), 8 warps (4m x 2n), warp tile 32x64, BK=32, 2-stage
__global__ void __launch_bounds__(256, 1)
g1_kernel(const float* __restrict__ b1) {
    extern __shared__ char dsm[];
    uint32_t sbase = (smem_u32(dsm) + 127u) & ~127u;
    const int i0 = blockIdx.y * 128, n0 = blockIdx.x * 128;
    const int tid = threadIdx.x, w = tid >> 5, lane = tid & 31;
    const int wm = w & 3, wn = w >> 2;
    const int NT = DIN / 32;          // 32
    const int STG = 6 * BUF32;        // 61440

    auto load_tile = [&](int kt, int st) {
        uint32_t sb = sbase + st * STG;
#pragma unroll
        for (int c = 0; c < 2; c++) {
            int idx = tid + c * 256, row = idx >> 2, c16 = idx & 3;
            uint32_t so = (uint32_t)(row * ROWB32 + c16 * 16);
            size_t ga = (size_t)(i0 + row) * DIN + kt * 32 + c16 * 8;
            size_t gb = (size_t)(n0 + row) * DIN + kt * 32 + c16 * 8;
            cpa(sb + 0 * BUF32 + so, g_xhi + ga);
            cpa(sb + 1 * BUF32 + so, g_xlo + ga);
            cpa(sb + 2 * BUF32 + so, g_xq  + ga);
            cpa(sb + 3 * BUF32 + so, g_whi + gb);
            cpa(sb + 4 * BUF32 + so, g_wlo + gb);
            cpa(sb + 5 * BUF32 + so, g_wq  + gb);
        }
        CP_COMMIT();
    };

    uint32_t aRow[2], bRow[4];
#pragma unroll
    for (int mt = 0; mt < 2; mt++)
        aRow[mt] = (uint32_t)((wm * 32 + mt * 16 + (lane & 15)) * ROWB32);
#pragma unroll
    for (int p = 0; p < 4; p++)
        bRow[p] = (uint32_t)((wn * 64 + p * 16 + ((lane >> 4) << 3) + (lane & 7)) * ROWB32);
    uint32_t aK = (uint32_t)((lane >> 4) * 16);
    uint32_t bK = (uint32_t)(((lane >> 3) & 1) * 16);

    float accF[2][8][4], accQ[2][8][4];
#pragma unroll
    for (int mt = 0; mt < 2; mt++)
#pragma unroll
        for (int nt = 0; nt < 8; nt++)
#pragma unroll
            for (int r = 0; r < 4; r++) { accF[mt][nt][r] = 0.f; accQ[mt][nt][r] = 0.f; }

    load_tile(0, 0);
    load_tile(1, 1);
    for (int kt = 0; kt < NT; kt++) {
        int st = kt & 1;
        if (kt + 2 < NT) CP_WAIT(1); else CP_WAIT(0);
        __syncthreads();
        uint32_t sb = sbase + st * STG;
#pragma unroll
        for (int kk = 0; kk < 2; kk++) {
            uint32_t ka = aK + kk * 32;
            uint32_t kb = bK + kk * 32;
            uint32_t ah[2][4], al[2][4], aq[2][4];
#pragma unroll
            for (int mt = 0; mt < 2; mt++) {
                ldsm4(ah[mt], sb + 0 * BUF32 + aRow[mt] + ka);
                ldsm4(al[mt], sb + 1 * BUF32 + aRow[mt] + ka);
                ldsm4(aq[mt], sb + 2 * BUF32 + aRow[mt] + ka);
            }
            uint32_t bh[8][2], bl[8][2], bq[8][2];
#pragma unroll
            for (int p = 0; p < 4; p++) {
                uint32_t t[4];
                ldsm4(t, sb + 3 * BUF32 + bRow[p] + kb);
                bh[2*p][0]=t[0]; bh[2*p][1]=t[1]; bh[2*p+1][0]=t[2]; bh[2*p+1][1]=t[3];
                ldsm4(t, sb + 4 * BUF32 + bRow[p] + kb);
                bl[2*p][0]=t[0]; bl[2*p][1]=t[1]; bl[2*p+1][0]=t[2]; bl[2*p+1][1]=t[3];
                ldsm4(t, sb + 5 * BUF32 + bRow[p] + kb);
                bq[2*p][0]=t[0]; bq[2*p][1]=t[1]; bq[2*p+1][0]=t[2]; bq[2*p+1][1]=t[3];
            }
#pragma unroll
            for (int mt = 0; mt < 2; mt++)
#pragma unroll
                for (int nt = 0; nt < 8; nt++) {
                    mma_bf16(accF[mt][nt], ah[mt], bh[nt]);
                    mma_bf16(accF[mt][nt], ah[mt], bl[nt]);
                    mma_bf16(accF[mt][nt], al[mt], bh[nt]);
                    mma_bf16(accQ[mt][nt], aq[mt], bq[nt]);
                }
        }
        __syncthreads();
        if (kt + 2 < NT) load_tile(kt + 2, st);
    }

    __shared__ float sb1[128], ssw[128], sqb[128], ssx[128];
    __shared__ int scnt[128];
    if (tid < 128) {
        int h = n0 + tid;
        sb1[tid] = b1[h]; ssw[tid] = g_sw[h]; sqb[tid] = g_qb[h];
        scnt[tid] = g_counts[h];
        ssx[tid] = g_sx[i0 + tid];
    }
    __syncthreads();

    int gq = lane >> 2, q4 = lane & 3;
#pragma unroll
    for (int mt = 0; mt < 2; mt++)
#pragma unroll
        for (int half = 0; half < 2; half++) {
            int rl = wm * 32 + mt * 16 + gq + half * 8;
            float sxv = ssx[rl];
            size_t ro = (size_t)(i0 + rl) * HID + n0;
#pragma unroll
            for (int nt = 0; nt < 8; nt++) {
                int cl = wn * 64 + nt * 8 + q4 * 2;
                float f0 = accF[mt][nt][half*2+0], f1 = accF[mt][nt][half*2+1];
                float q0 = accQ[mt][nt][half*2+0], q1 = accQ[mt][nt][half*2+1];
                float v0 = (scnt[cl]   > THRESH) ? (f0 + sb1[cl])
                          : fmaf(sxv * ssw[cl],   q0, sqb[cl]);
                float v1 = (scnt[cl+1] > THRESH) ? (f1 + sb1[cl+1])
                          : fmaf(sxv * ssw[cl+1], q1, sqb[cl+1]);
                float g0 = gelu_exact(v0), g1 = gelu_exact(v1);
                __nv_bfloat162 hi, lo;
                hi.x = __float2bfloat16(g0); hi.y = __float2bfloat16(g1);
                lo.x = __float2bfloat16(g0 - __bfloat162float(hi.x));
                lo.y = __float2bfloat16(g1 - __bfloat162float(hi.y));
                *(uint32_t*)(g_hhi + ro + cl) = *(uint32_t*)&hi;
                *(uint32_t*)(g_hlo + ro + cl) = *(uint32_t*)&lo;
            }
        }
}

// ================= topk: HMMA split GEMM over padded K=128, vote count =========
__global__ void __launch_bounds__(256, 1)
topk_kernel(const float* __restrict__ b1) {
    extern __shared__ char dsm[];
    uint32_t sbase = (smem_u32(dsm) + 127u) & ~127u;
    const int i0 = blockIdx.y * 128, n0 = blockIdx.x * 128;
    const int tid = threadIdx.x, w = tid >> 5, lane = tid & 31;
    const int wm = w & 3, wn = w >> 2;
    const int NT = 2;
    const int STG = 4 * BUF;

    auto load_tile = [&](int kt, int st) {
        uint32_t sb = sbase + st * STG;
#pragma unroll
        for (int c = 0; c < 4; c++) {
            int idx = tid + c * 256, row = idx >> 3, c16 = idx & 7;
            uint32_t so = (uint32_t)(row * ROWB + c16 * 16);
            size_t ga = (size_t)(i0 + row) * KTP + kt * 64 + c16 * 8;
            size_t gb = (size_t)(n0 + row) * KTP + kt * 64 + c16 * 8;
            cpa(sb + 0 * BUF + so, g_xthi + ga);
            cpa(sb + 1 * BUF + so, g_xtlo + ga);
            cpa(sb + 2 * BUF + so, g_wthi + gb);
            cpa(sb + 3 * BUF + so, g_wtlo + gb);
        }
        CP_COMMIT();
    };

    uint32_t aRow[2], bRow[4];
#pragma unroll
    for (int mt = 0; mt < 2; mt++)
        aRow[mt] = (uint32_t)((wm * 32 + mt * 16 + (lane & 15)) * ROWB);
#pragma unroll
    for (int p = 0; p < 4; p++)
        bRow[p] = (uint32_t)((wn * 64 + p * 16 + ((lane >> 4) << 3) + (lane & 7)) * ROWB);
    uint32_t aK = (uint32_t)((lane >> 4) * 16);
    uint32_t bK = (uint32_t)(((lane >> 3) & 1) * 16);

    float acc[2][8][4];
#pragma unroll
    for (int mt = 0; mt < 2; mt++)
#pragma unroll
        for (int nt = 0; nt < 8; nt++)
#pragma unroll
            for (int r = 0; r < 4; r++) acc[mt][nt][r] = 0.f;

    load_tile(0, 0);
    load_tile(1, 1);
    for (int kt = 0; kt < NT; kt++) {
        int st = kt & 1;
        CP_WAIT(0);
        __syncthreads();
        uint32_t sb = sbase + st * STG;
#pragma unroll
        for (int kk = 0; kk < 4; kk++) {
            uint32_t ka = aK + kk * 32;
            uint32_t kb = bK + kk * 32;
            uint32_t ah[2][4], al[2][4];
#pragma unroll
            for (int mt = 0; mt < 2; mt++) {
                ldsm4(ah[mt], sb + 0 * BUF + aRow[mt] + ka);
                ldsm4(al[mt], sb + 1 * BUF + aRow[mt] + ka);
            }
            uint32_t bh[8][2], bl[8][2];
#pragma unroll
            for (int p = 0; p < 4; p++) {
                uint32_t t[4];
                ldsm4(t, sb + 2 * BUF + bRow[p] + kb);
                bh[2*p][0]=t[0]; bh[2*p][1]=t[1]; bh[2*p+1][0]=t[2]; bh[2*p+1][1]=t[3];
                ldsm4(t, sb + 3 * BUF + bRow[p] + kb);
                bl[2*p][0]=t[0]; bl[2*p][1]=t[1]; bl[2*p+1][0]=t[2]; bl[2*p+1][1]=t[3];
            }
#pragma unroll
            for (int mt = 0; mt < 2; mt++)
#pragma unroll
                for (int nt = 0; nt < 8; nt++) {
                    mma_bf16(acc[mt][nt], ah[mt], bh[nt]);
                    mma_bf16(acc[mt][nt], ah[mt], bl[nt]);
                    mma_bf16(acc[mt][nt], al[mt], bh[nt]);
                }
        }
        __syncthreads();
    }

    __shared__ float sb1[128];
    __shared__ int scnt[128];
    if (tid < 128) { sb1[tid] = b1[n0 + tid]; scnt[tid] = 0; }
    __syncthreads();

    int q4 = lane & 3;
#pragma unroll
    for (int nt = 0; nt < 8; nt++) {
        int cl = wn * 64 + nt * 8 + q4 * 2;
        int c0 = 0, c1 = 0;
#pragma unroll
        for (int mt = 0; mt < 2; mt++)
#pragma unroll
            for (int half = 0; half < 2; half++) {
                c0 += (acc[mt][nt][half*2+0] + sb1[cl]   > 0.f);
                c1 += (acc[mt][nt][half*2+1] + sb1[cl+1] > 0.f);
            }
        atomicAdd(&scnt[cl],     c0);
        atomicAdd(&scnt[cl + 1], c1);
    }
    __syncthreads();
    if (tid < 128) atomicAdd(&g_counts[n0 + tid], scnt[tid]);
}

// ================= G2: HMMA out = h @ W2^T + b2 (byte-identical to proven R5) ==
__global__ void __launch_bounds__(256, 1)
g2_kernel(const float* __restrict__ b2, float* __restrict__ out) {
    extern __shared__ char dsm[];
    uint32_t sbase = (smem_u32(dsm) + 127u) & ~127u;
    const int i0 = blockIdx.y * 128, d0 = blockIdx.x * 128;
    const int tid = threadIdx.x, w = tid >> 5, lane = tid & 31;
    const int wm = w & 3, wn = w >> 2;
    const int NT = HID / 64;
    const int STG = 4 * BUF;

    auto load_tile = [&](int kt, int st) {
        uint32_t sb = sbase + st * STG;
#pragma unroll
        for (int c = 0; c < 4; c++) {
            int idx = tid + c * 256, row = idx >> 3, c16 = idx & 7;
            uint32_t so = (uint32_t)(row * ROWB + c16 * 16);
            size_t ga = (size_t)(i0 + row) * HID + kt * 64 + c16 * 8;
            size_t gb = (size_t)(d0 + row) * HID + kt * 64 + c16 * 8;
            cpa(sb + 0 * BUF + so, g_hhi  + ga);
            cpa(sb + 1 * BUF + so, g_hlo  + ga);
            cpa(sb + 2 * BUF + so, g_w2hi + gb);
            cpa(sb + 3 * BUF + so, g_w2lo + gb);
        }
        CP_COMMIT();
    };

    uint32_t aRow[2], bRow[4];
#pragma unroll
    for (int mt = 0; mt < 2; mt++)
        aRow[mt] = (uint32_t)((wm * 32 + mt * 16 + (lane & 15)) * ROWB);
#pragma unroll
    for (int p = 0; p < 4; p++)
        bRow[p] = (uint32_t)((wn * 64 + p * 16 + ((lane >> 4) << 3) + (lane & 7)) * ROWB);
    uint32_t aK = (uint32_t)((lane >> 4) * 16);
    uint32_t bK = (uint32_t)(((lane >> 3) & 1) * 16);

    float acc[2][8][4];
#pragma unroll
    for (int mt = 0; mt < 2; mt++)
#pragma unroll
        for (int nt = 0; nt < 8; nt++)
#pragma unroll
            for (int r = 0; r < 4; r++) acc[mt][nt][r] = 0.f;

    load_tile(0, 0);
    load_tile(1, 1);
    for (int kt = 0; kt < NT; kt++) {
        int st = kt & 1;
        if (kt + 2 < NT) CP_WAIT(1); else CP_WAIT(0);
        __syncthreads();
        uint32_t sb = sbase + st * STG;
#pragma unroll
        for (int kk = 0; kk < 4; kk++) {
            uint32_t ka = aK + kk * 32;
            uint32_t kb = bK + kk * 32;
            uint32_t ah[2][4], al[2][4];
#pragma unroll
            for (int mt = 0; mt < 2; mt++) {
                ldsm4(ah[mt], sb + 0 * BUF + aRow[mt] + ka);
                ldsm4(al[mt], sb + 1 * BUF + aRow[mt] + ka);
            }
            uint32_t bh[8][2], bl[8][2];
#pragma unroll
            for (int p = 0; p < 4; p++) {
                uint32_t t[4];
                ldsm4(t, sb + 2 * BUF + bRow[p] + kb);
                bh[2*p][0]=t[0]; bh[2*p][1]=t[1]; bh[2*p+1][0]=t[2]; bh[2*p+1][1]=t[3];
                ldsm4(t, sb + 3 * BUF + bRow[p] + kb);
                bl[2*p][0]=t[0]; bl[2*p][1]=t[1]; bl[2*p+1][0]=t[2]; bl[2*p+1][1]=t[3];
            }
#pragma unroll
            for (int mt = 0; mt < 2; mt++)
#pragma unroll
                for (int nt = 0; nt < 8; nt++) {
                    mma_bf16(acc[mt][nt], ah[mt], bh[nt]);
                    mma_bf16(acc[mt][nt], ah[mt], bl[nt]);
                    mma_bf16(acc[mt][nt], al[mt], bh[nt]);
                }
        }
        __syncthreads();
        if (kt + 2 < NT) load_tile(kt + 2, st);
    }

    __shared__ float sbb[128];
    if (tid < 128) sbb[tid] = b2[d0 + tid];
    __syncthreads();

    int gq = lane >> 2, q4 = lane & 3;
#pragma unroll
    for (int mt = 0; mt < 2; mt++)
#pragma unroll
        for (int half = 0; half < 2; half++) {
            int rl = wm * 32 + mt * 16 + gq + half * 8;
            float* dst = out + (size_t)(i0 + rl) * DIN + d0;
#pragma unroll
            for (int nt = 0; nt < 8; nt++) {
                int cl = wn * 64 + nt * 8 + q4 * 2;
                float2 o = make_float2(acc[mt][nt][half*2+0] + sbb[cl],
                                       acc[mt][nt][half*2+1] + sbb[cl+1]);
                *(float2*)(dst + cl) = o;
            }
        }
}

// ---------------- prep kernels (globals referenced in DEVICE code only!) --------
__global__ void prep_rows_kernel(const float* __restrict__ src, int which) {
    bf16 *hi, *lo, *qb, *thi, *tlo;
    float* scales;
    if (which) { hi = g_whi; lo = g_wlo; qb = g_wq; scales = g_sw;
                 thi = g_wthi; tlo = g_wtlo; }
    else       { hi = g_xhi; lo = g_xlo; qb = g_xq; scales = g_sx;
                 thi = g_xthi; tlo = g_xtlo; }

    int row = blockIdx.x, tid = threadIdx.x;
    const float* r = src + (size_t)row * DIN;
    float4 v = ((const float4*)r)[tid];
    float amax = fmaxf(fmaxf(fabsf(v.x), fabsf(v.y)), fmaxf(fabsf(v.z), fabsf(v.w)));
    __shared__ float red[256];
    red[tid] = amax; __syncthreads();
    for (int s = 128; s; s >>= 1) {
        if (tid < s) red[tid] = fmaxf(red[tid], red[tid + s]);
        __syncthreads();
    }
    float scale = fmaxf(red[0], 1e-5f) / 127.f;
    if (tid == 0) scales[row] = scale;
    float e[4] = {v.x, v.y, v.z, v.w};
    __nv_bfloat162 h2[2], l2[2], q2[2];
#pragma unroll
    for (int k = 0; k < 4; k++) {
        bf16 hb = __float2bfloat16(e[k]);
        bf16 lb = __float2bfloat16(e[k] - __bfloat162float(hb));
        float qq = fminf(127.f, fmaxf(-128.f, rintf(e[k] / scale)));
        bf16 qv = __float2bfloat16(qq);
        if (k & 1) { h2[k>>1].y = hb; l2[k>>1].y = lb; q2[k>>1].y = qv; }
        else       { h2[k>>1].x = hb; l2[k>>1].x = lb; q2[k>>1].x = qv; }
    }
    size_t o = (size_t)row * DIN + tid * 4;
    *(uint2*)(hi + o) = make_uint2(*(uint32_t*)&h2[0], *(uint32_t*)&h2[1]);
    *(uint2*)(lo + o) = make_uint2(*(uint32_t*)&l2[0], *(uint32_t*)&l2[1]);
    *(uint2*)(qb + o) = make_uint2(*(uint32_t*)&q2[0], *(uint32_t*)&q2[1]);
    if (tid < KTP) {
        float val = (tid < TOPKC) ? r[tid] : 0.f;
        bf16 hb = __float2bfloat16(val);
        thi[(size_t)row * KTP + tid] = hb;
        tlo[(size_t)row * KTP + tid] = __float2bfloat16(val - __bfloat162float(hb));
    }
}

__global__ void prep_w2_kernel(const float* __restrict__ W2) {
    int row = blockIdx.x, tid = threadIdx.x;
    const float4* r = (const float4*)(W2 + (size_t)row * HID);
#pragma unroll
    for (int j = 0; j < 4; j++) {
        float4 v = r[tid + 256 * j];
        float e[4] = {v.x, v.y, v.z, v.w};
        __nv_bfloat162 h2[2], l2[2];
#pragma unroll
        for (int k = 0; k < 4; k++) {
            bf16 hb = __float2bfloat16(e[k]);
            bf16 lb = __float2bfloat16(e[k] - __bfloat162float(hb));
            if (k & 1) { h2[k>>1].y = hb; l2[k>>1].y = lb; }
            else       { h2[k>>1].x = hb; l2[k>>1].x = lb; }
        }
        size_t o = (size_t)row * HID + (tid + 256 * j) * 4;
        *(uint2*)(g_w2hi + o) = make_uint2(*(uint32_t*)&h2[0], *(uint32_t*)&h2[1]);
        *(uint2*)(g_w2lo + o) = make_uint2(*(uint32_t*)&l2[0], *(uint32_t*)&l2[1]);
    }
}

__global__ void prep_b1_kernel(const float* __restrict__ b1) {
    __shared__ float red[256];
    int tid = threadIdx.x;
    float amax = 0.f;
    for (int i = tid; i < HID; i += 256) amax = fmaxf(amax, fabsf(b1[i]));
    red[tid] = amax; __syncthreads();
    for (int s = 128; s; s >>= 1) {
        if (tid < s) red[tid] = fmaxf(red[tid], red[tid + s]);
        __syncthreads();
    }
    float scale = fmaxf(red[0], 1e-5f) / 127.f;
    for (int i = tid; i < HID; i += 256) {
        g_qb[i] = fminf(127.f, fmaxf(-128.f, rintf(b1[i] / scale))) * scale;
        g_counts[i] = 0;
    }
}

// ---------------- launch -----------------------------------------------------------
extern "C" void kernel_launch(void* const* d_in, const int* in_sizes, int n_in,
                              void* d_out, int out_size) {
    const float* x  = (const float*)d_in[0];
    const float* W1 = (const float*)d_in[1];
    const float* b1 = (const float*)d_in[2];
    const float* W2 = (const float*)d_in[3];
    const float* b2 = (const float*)d_in[4];
    float* out = (float*)d_out;

    const int SM_G1 = 2 * 6 * BUF32 + 256;   // 123136
    const int SM_TK = 2 * 4 * BUF + 256;     // 147712 (proven size)
    const int SM_G2 = 2 * 4 * BUF + 256;     // 147712 (proven size)
    cudaFuncSetAttribute(g1_kernel,   cudaFuncAttributeMaxDynamicSharedMemorySize, SM_G1);
    cudaFuncSetAttribute(topk_kernel, cudaFuncAttributeMaxDynamicSharedMemorySize, SM_TK);
    cudaFuncSetAttribute(g2_kernel,   cudaFuncAttributeMaxDynamicSharedMemorySize, SM_G2);

    prep_b1_kernel<<<1, 256>>>(b1);          // also zeroes g_counts
    prep_rows_kernel<<<NTOK, 256>>>(x, 0);
    prep_rows_kernel<<<HID,  256>>>(W1, 1);
    prep_w2_kernel<<<DIN, 256>>>(W2);

    dim3 gt(HID / 128, NTOK / 128);   // (32, 64)
    topk_kernel<<<gt, 256, SM_TK>>>(b1);
    g1_kernel<<<gt, 256, SM_G1>>>(b1);
    dim3 gg2(DIN / 128, NTOK / 128);  // (8, 64)
    g2_kernel<<<gg2, 256, SM_G2>>>(b2, out);
}